// round 12
// baseline (speedup 1.0000x reference)
#include <cuda_runtime.h>
#include <cuda_bf16.h>

#define NMAX 4096
#define BIGF 1e30f
#define TILE 128
#define NB 148           // persistent blocks; <= SM count -> co-resident guaranteed

// Scratch (__device__ globals; allocation is forbidden)
__device__ float4 g_rows[NMAX];        // compacted m1: (hx, hy, hz, rr)
__device__ float4 g_cols[NMAX];        // compacted m2: (px, py, pz, -0.5*cc)
__device__ unsigned int g_d1[NMAX];    // per m2-col slot: min over m1 rows (float bits)
__device__ unsigned int g_d2[NMAX];    // per m1-row slot: min over m2 cols (float bits)
__device__ int g_cnt[2] = {0, 0};      // {nr, nc}; reduce_kernel re-zeroes
__device__ int g_bar = 0;              // grid barrier (monotonic); reduce re-zeroes

// ---------------------------------------------------------------------------
// Fused prep + dist. Phase 1: all NB blocks classify/compact their slice of
// points (warp-aggregated global atomics; slot order nondeterministic but all
// consumers are order-invariant min/sum). Phase 2 (after monotonic grid spin
// barrier): persistent tile loop over compacted nr x nc.
//   u = dot(r,c) - 0.5cc; row min = rr - 2*max_c u; col min = min_r fma(u,-2,rr)
// ---------------------------------------------------------------------------
__global__ void __launch_bounds__(256, 2) fused_kernel(const float* __restrict__ norm,
                                                       const float* __restrict__ pts,
                                                       int n) {
    __shared__ float4 srow[TILE];
    __shared__ float4 scol[TILE];
    __shared__ unsigned int credu[TILE];
    __shared__ unsigned int rredu[TILE];
    __shared__ int s_nr, s_nc;

    int t = threadIdx.x;
    int lane = t & 31;

    float nx = __ldg(norm), ny = __ldg(norm + 1), nz = __ldg(norm + 2), dd = __ldg(norm + 3);
    float nn = nx * nx + ny * ny + nz * nz;

    // ---- phase 1: prep (one pass; NB*256 = 37888 threads >= n for n<=4096*9) ----
    for (int i = blockIdx.x * 256 + t; i < n; i += NB * 256) {
        float px = pts[3 * i], py = pts[3 * i + 1], pz = pts[3 * i + 2];
        float ts = -2.0f * (px * nx + py * ny + pz * nz + dd);
        bool m1 = ts > 0.0f;
        g_d1[i] = __float_as_uint(BIGF);
        g_d2[i] = __float_as_uint(BIGF);

        unsigned lanelt = (1u << lane) - 1u;
        unsigned act = __activemask();
        unsigned mk1 = __ballot_sync(act, m1);
        unsigned mk2 = mk1 ^ act;
        if (mk1) {
            int leader = __ffs(mk1) - 1;
            int base = 0;
            if (lane == leader) base = atomicAdd(&g_cnt[0], __popc(mk1));
            base = __shfl_sync(act, base, leader);
            if (m1) {
                float kk = ts / nn;
                float hx = fmaf(kk, nx, px), hy = fmaf(kk, ny, py), hz = fmaf(kk, nz, pz);
                float rr = fmaf(hx, hx, fmaf(hy, hy, hz * hz));
                g_rows[base + __popc(mk1 & lanelt)] = make_float4(hx, hy, hz, rr);
            }
        }
        if (mk2) {
            int leader = __ffs(mk2) - 1;
            int base = 0;
            if (lane == leader) base = atomicAdd(&g_cnt[1], __popc(mk2));
            base = __shfl_sync(act, base, leader);
            if (!m1) {
                float cc = fmaf(px, px, fmaf(py, py, pz * pz));
                g_cols[base + __popc(mk2 & lanelt)] = make_float4(px, py, pz, -0.5f * cc);
            }
        }
    }

    // ---- grid barrier (monotonic counter; reset later by reduce_kernel) ----
    __syncthreads();
    if (t == 0) {
        __threadfence();
        atomicAdd(&g_bar, 1);
        while (atomicAdd(&g_bar, 0) < NB) { }
        s_nr = atomicAdd(&g_cnt[0], 0);   // atomic read: L2-coherent, bypasses L1
        s_nc = atomicAdd(&g_cnt[1], 0);
    }
    __syncthreads();
    int nr = s_nr;
    int nc = s_nc;

    // ---- phase 2: dist over compacted nr x nc ----
    int ntr = (nr + TILE - 1) / TILE;
    int ntc = (nc + TILE - 1) / TILE;
    int ntiles = ntr * ntc;
    int tx = t & 15, ty = t >> 4;

    for (int tile = blockIdx.x; tile < ntiles; tile += NB) {
        int by = tile / ntc;
        int bx = tile - by * ntc;
        int i0 = by * TILE;
        int j0 = bx * TILE;

        __syncthreads();                  // protect smem reuse across iterations
        if (t < TILE) {
            int gi = i0 + t;
            srow[t] = (gi < nr) ? g_rows[gi] : make_float4(0.f, 0.f, 0.f, BIGF);
            credu[t] = __float_as_uint(BIGF);
        } else {
            int u = t - TILE;
            int gj = j0 + u;
            scol[u] = (gj < nc) ? g_cols[gj] : make_float4(0.f, 0.f, 0.f, -BIGF);
            rredu[u] = __float_as_uint(BIGF);
        }
        __syncthreads();

        float RX[8], RY[8], RZ[8], RA[8];
#pragma unroll
        for (int r = 0; r < 8; r++) {
            float4 v = srow[ty * 8 + r];
            RX[r] = v.x; RY[r] = v.y; RZ[r] = v.z; RA[r] = v.w;   // rr (or BIG pad)
        }
        float CX[8], CY[8], CZ[8], CI[8];
#pragma unroll
        for (int c = 0; c < 8; c++) {
            float4 v = scol[c * 16 + tx];   // consecutive tx -> conflict-free
            CX[c] = v.x; CY[c] = v.y; CZ[c] = v.z; CI[c] = v.w;   // -0.5cc (or -BIG pad)
        }

        float cmin[8], umax[8];
#pragma unroll
        for (int k = 0; k < 8; k++) { cmin[k] = BIGF; umax[k] = -BIGF; }

#pragma unroll
        for (int r = 0; r < 8; r++) {
            float rxv = RX[r], ryv = RY[r], rzv = RZ[r], Av = RA[r];
            float um = umax[r];
#pragma unroll
            for (int c = 0; c < 8; c++) {
                float u = fmaf(rzv, CZ[c], fmaf(ryv, CY[c], fmaf(rxv, CX[c], CI[c])));
                um      = fmaxf(um, u);
                cmin[c] = fminf(cmin[c], fmaf(u, -2.0f, Av));
            }
            umax[r] = um;
        }

        // block-level combine (clamped >= 0 so uint order == float order)
#pragma unroll
        for (int c = 0; c < 8; c++)
            atomicMin(&credu[c * 16 + tx], __float_as_uint(fmaxf(cmin[c], 0.0f)));
#pragma unroll
        for (int r = 0; r < 8; r++) {
            float v = fmaxf(fmaf(umax[r], -2.0f, RA[r]), 0.0f);   // rr - 2*umax
            atomicMin(&rredu[ty * 8 + r], __float_as_uint(v));
        }
        __syncthreads();

        if (t < TILE) {
            int gj = j0 + t;
            if (gj < nc) atomicMin(&g_d1[gj], credu[t]);
        } else {
            int u = t - TILE;
            int gi = i0 + u;
            if (gi < nr) atomicMin(&g_d2[gi], rredu[u]);
        }
    }
}

// ---------------------------------------------------------------------------
// Reduce: sums over compacted ranges; restores g_cnt/g_bar for next replay.
// ---------------------------------------------------------------------------
__global__ void __launch_bounds__(1024) reduce_kernel(float* __restrict__ out) {
    int t = threadIdx.x;
    int nr = g_cnt[0];
    int nc = g_cnt[1];
    int m = nr > nc ? nr : nc;
    float s1 = 0.f, s2 = 0.f;
    for (int i = t; i < m; i += 1024) {
        if (i < nc) s1 += __uint_as_float(g_d1[i]);
        if (i < nr) s2 += __uint_as_float(g_d2[i]);
    }
#pragma unroll
    for (int o = 16; o > 0; o >>= 1) {
        s1 += __shfl_xor_sync(0xffffffffu, s1, o);
        s2 += __shfl_xor_sync(0xffffffffu, s2, o);
    }
    __shared__ float sh[2][32];
    int w = t >> 5, l = t & 31;
    if (l == 0) { sh[0][w] = s1; sh[1][w] = s2; }
    __syncthreads();
    if (t == 0) { g_cnt[0] = 0; g_cnt[1] = 0; g_bar = 0; }   // restore replay state
    if (w == 0) {
        float a = sh[0][l], b = sh[1][l];
#pragma unroll
        for (int o = 16; o > 0; o >>= 1) {
            a += __shfl_xor_sync(0xffffffffu, a, o);
            b += __shfl_xor_sync(0xffffffffu, b, o);
        }
        if (l == 0) {
            float c2 = fmaxf((float)nc, 1.0f);   // m2 count (av1 divisor)
            float c1 = fmaxf((float)nr, 1.0f);   // m1 count (av2 divisor)
            out[0] = (0.5f * (a / c2) + 0.5f * (b / c1)) * 100.0f;
        }
    }
}

// ---------------------------------------------------------------------------
extern "C" void kernel_launch(void* const* d_in, const int* in_sizes, int n_in,
                              void* d_out, int out_size) {
    const float* a0 = (const float*)d_in[0];
    const float* a1 = (const float*)d_in[1];
    const float* norm;
    const float* pts;
    int n;
    if (in_sizes[0] == 4) { norm = a0; pts = a1; n = in_sizes[1] / 3; }
    else                  { norm = a1; pts = a0; n = in_sizes[0] / 3; }

    float* out = (float*)d_out;

    fused_kernel<<<NB, 256>>>(norm, pts, n);
    reduce_kernel<<<1, 1024>>>(out);
}

// round 13
// speedup vs baseline: 1.0718x; 1.0718x over previous
#include <cuda_runtime.h>
#include <cuda_bf16.h>

#define NMAX 4096
#define BIGF 1e30f
#define TILE 128
#define NB 148           // persistent blocks; <= SM count -> co-resident guaranteed

// Scratch (__device__ globals; allocation is forbidden)
__device__ float4 g_rows[NMAX];        // compacted m1: (hx, hy, hz, rr)
__device__ float4 g_cols[NMAX];        // compacted m2: (px, py, pz, -0.5*cc)
__device__ unsigned int g_d1[NMAX];    // per m2-col slot: min over m1 rows (float bits)
__device__ unsigned int g_d2[NMAX];    // per m1-row slot: min over m2 cols (float bits)
__device__ int g_cnt[2] = {0, 0};      // {nr, nc}; block 0 re-zeroes at end
__device__ int g_bar = 0;              // monotonic barrier counter; block 0 re-zeroes

// ---------------------------------------------------------------------------
// Single fused kernel: prep -> barrier -> dist -> barrier -> block-0 reduce.
// Barrier is a monotonic counter: phase 1 waits for NB, phase 2 only block 0
// waits for 2*NB (other blocks arrive and exit). Reset at the very end by
// block 0, after every other block has finished -> graph-replay determinism.
// ---------------------------------------------------------------------------
__global__ void __launch_bounds__(256, 2) fused_kernel(const float* __restrict__ norm,
                                                       const float* __restrict__ pts,
                                                       float* __restrict__ out,
                                                       int n) {
    __shared__ float4 srow[TILE];
    __shared__ float4 scol[TILE];
    __shared__ unsigned int credu[TILE];
    __shared__ unsigned int rredu[TILE];
    __shared__ int s_nr, s_nc;
    __shared__ float sh[2][8];

    int t = threadIdx.x;
    int lane = t & 31;

    float nx = __ldg(norm), ny = __ldg(norm + 1), nz = __ldg(norm + 2), dd = __ldg(norm + 3);
    float nn = nx * nx + ny * ny + nz * nz;

    // ---- phase 1: prep (classify + compact via warp-aggregated atomics) ----
    for (int i = blockIdx.x * 256 + t; i < n; i += NB * 256) {
        float px = pts[3 * i], py = pts[3 * i + 1], pz = pts[3 * i + 2];
        float ts = -2.0f * (px * nx + py * ny + pz * nz + dd);
        bool m1 = ts > 0.0f;
        g_d1[i] = __float_as_uint(BIGF);
        g_d2[i] = __float_as_uint(BIGF);

        unsigned lanelt = (1u << lane) - 1u;
        unsigned act = __activemask();
        unsigned mk1 = __ballot_sync(act, m1);
        unsigned mk2 = mk1 ^ act;
        if (mk1) {
            int leader = __ffs(mk1) - 1;
            int base = 0;
            if (lane == leader) base = atomicAdd(&g_cnt[0], __popc(mk1));
            base = __shfl_sync(act, base, leader);
            if (m1) {
                float kk = ts / nn;
                float hx = fmaf(kk, nx, px), hy = fmaf(kk, ny, py), hz = fmaf(kk, nz, pz);
                float rr = fmaf(hx, hx, fmaf(hy, hy, hz * hz));
                g_rows[base + __popc(mk1 & lanelt)] = make_float4(hx, hy, hz, rr);
            }
        }
        if (mk2) {
            int leader = __ffs(mk2) - 1;
            int base = 0;
            if (lane == leader) base = atomicAdd(&g_cnt[1], __popc(mk2));
            base = __shfl_sync(act, base, leader);
            if (!m1) {
                float cc = fmaf(px, px, fmaf(py, py, pz * pz));
                g_cols[base + __popc(mk2 & lanelt)] = make_float4(px, py, pz, -0.5f * cc);
            }
        }
    }

    // ---- barrier 1: all blocks ----
    __syncthreads();
    if (t == 0) {
        __threadfence();
        atomicAdd(&g_bar, 1);
        while (atomicAdd(&g_bar, 0) < NB) { }
        s_nr = atomicAdd(&g_cnt[0], 0);
        s_nc = atomicAdd(&g_cnt[1], 0);
    }
    __syncthreads();
    int nr = s_nr;
    int nc = s_nc;

    // ---- phase 2: dist over compacted nr x nc ----
    int ntr = (nr + TILE - 1) / TILE;
    int ntc = (nc + TILE - 1) / TILE;
    int ntiles = ntr * ntc;
    int tx = t & 15, ty = t >> 4;

    for (int tile = blockIdx.x; tile < ntiles; tile += NB) {
        int by = tile / ntc;
        int bx = tile - by * ntc;
        int i0 = by * TILE;
        int j0 = bx * TILE;

        __syncthreads();                  // protect smem reuse across iterations
        if (t < TILE) {
            int gi = i0 + t;
            srow[t] = (gi < nr) ? g_rows[gi] : make_float4(0.f, 0.f, 0.f, BIGF);
            credu[t] = __float_as_uint(BIGF);
        } else {
            int u = t - TILE;
            int gj = j0 + u;
            scol[u] = (gj < nc) ? g_cols[gj] : make_float4(0.f, 0.f, 0.f, -BIGF);
            rredu[u] = __float_as_uint(BIGF);
        }
        __syncthreads();

        float RX[8], RY[8], RZ[8], RA[8];
#pragma unroll
        for (int r = 0; r < 8; r++) {
            float4 v = srow[ty * 8 + r];
            RX[r] = v.x; RY[r] = v.y; RZ[r] = v.z; RA[r] = v.w;   // rr (or BIG pad)
        }
        float CX[8], CY[8], CZ[8], CI[8];
#pragma unroll
        for (int c = 0; c < 8; c++) {
            float4 v = scol[c * 16 + tx];   // consecutive tx -> conflict-free
            CX[c] = v.x; CY[c] = v.y; CZ[c] = v.z; CI[c] = v.w;   // -0.5cc (or -BIG pad)
        }

        float cmin[8], umax[8];
#pragma unroll
        for (int k = 0; k < 8; k++) { cmin[k] = BIGF; umax[k] = -BIGF; }

#pragma unroll
        for (int r = 0; r < 8; r++) {
            float rxv = RX[r], ryv = RY[r], rzv = RZ[r], Av = RA[r];
            float um = umax[r];
#pragma unroll
            for (int c = 0; c < 8; c++) {
                float u = fmaf(rzv, CZ[c], fmaf(ryv, CY[c], fmaf(rxv, CX[c], CI[c])));
                um      = fmaxf(um, u);
                cmin[c] = fminf(cmin[c], fmaf(u, -2.0f, Av));
            }
            umax[r] = um;
        }

        // block-level combine (clamped >= 0 so uint order == float order)
#pragma unroll
        for (int c = 0; c < 8; c++)
            atomicMin(&credu[c * 16 + tx], __float_as_uint(fmaxf(cmin[c], 0.0f)));
#pragma unroll
        for (int r = 0; r < 8; r++) {
            float v = fmaxf(fmaf(umax[r], -2.0f, RA[r]), 0.0f);   // rr - 2*umax
            atomicMin(&rredu[ty * 8 + r], __float_as_uint(v));
        }
        __syncthreads();

        if (t < TILE) {
            int gj = j0 + t;
            if (gj < nc) atomicMin(&g_d1[gj], credu[t]);
        } else {
            int u = t - TILE;
            int gi = i0 + u;
            if (gi < nr) atomicMin(&g_d2[gi], rredu[u]);
        }
    }

    // ---- barrier 2: non-zero blocks arrive and exit; block 0 spins ----
    __syncthreads();
    if (blockIdx.x != 0) {
        if (t == 0) {
            __threadfence();
            atomicAdd(&g_bar, 1);
        }
        return;
    }
    if (t == 0) {
        __threadfence();
        atomicAdd(&g_bar, 1);
        while (atomicAdd(&g_bar, 0) < 2 * NB) { }
    }
    __syncthreads();

    // ---- phase 3 (block 0 only): final sums + output ----
    float s1 = 0.f, s2 = 0.f;
    int m = nr > nc ? nr : nc;
    for (int i = t; i < m; i += 256) {
        if (i < nc) s1 += __uint_as_float(__ldcg(&g_d1[i]));   // L2-coherent load
        if (i < nr) s2 += __uint_as_float(__ldcg(&g_d2[i]));
    }
#pragma unroll
    for (int o = 16; o > 0; o >>= 1) {
        s1 += __shfl_xor_sync(0xffffffffu, s1, o);
        s2 += __shfl_xor_sync(0xffffffffu, s2, o);
    }
    int w = t >> 5;
    if (lane == 0) { sh[0][w] = s1; sh[1][w] = s2; }
    __syncthreads();
    if (t == 0) {
        float a = 0.f, b = 0.f;
#pragma unroll
        for (int i = 0; i < 8; i++) { a += sh[0][i]; b += sh[1][i]; }
        float c2 = fmaxf((float)nc, 1.0f);   // m2 count (av1 divisor)
        float c1 = fmaxf((float)nr, 1.0f);   // m1 count (av2 divisor)
        out[0] = (0.5f * (a / c2) + 0.5f * (b / c1)) * 100.0f;
        g_cnt[0] = 0; g_cnt[1] = 0; g_bar = 0;   // restore replay state
        __threadfence();
    }
}

// ---------------------------------------------------------------------------
extern "C" void kernel_launch(void* const* d_in, const int* in_sizes, int n_in,
                              void* d_out, int out_size) {
    const float* a0 = (const float*)d_in[0];
    const float* a1 = (const float*)d_in[1];
    const float* norm;
    const float* pts;
    int n;
    if (in_sizes[0] == 4) { norm = a0; pts = a1; n = in_sizes[1] / 3; }
    else                  { norm = a1; pts = a0; n = in_sizes[0] / 3; }

    float* out = (float*)d_out;

    fused_kernel<<<NB, 256>>>(norm, pts, out, n);
}